// round 6
// baseline (speedup 1.0000x reference)
#include <cuda_runtime.h>
#include <cuda_bf16.h>

// Problem constants: x [4096, K*H], A/B [G, H, H], out [4096, G*K*H]
#define G_DIM 4
#define K_BLK 8
#define H_DIM 512
#define N_COLS (G_DIM * H_DIM)          // 2048 (weight output columns, g-major)
#define MAX_BSZ 4096

// ---------------------------------------------------------------------------
// Device scratch (static — no runtime allocation allowed)
// ---------------------------------------------------------------------------
__device__ float g_Wt[H_DIM * N_COLS];          // (A-B) transposed: Wt[h][g*512+p]  (4 MB)
__device__ float g_Bt[H_DIM * N_COLS];          // B transposed:     Bt[h][g*512+p]  (4 MB)
__device__ float g_S [MAX_BSZ * H_DIM];         // S[b][h] = sum_k x3[b,k,h]         (8 MB)
__device__ float g_T [MAX_BSZ * N_COLS];        // T[b][g*512+p] = S @ B_g^T        (32 MB)

// ---------------------------------------------------------------------------
// Prep: transpose weights.  Wt[h*2048 + g*512 + p] = A[g,p,h] - B[g,p,h]
//                           Bt[h*2048 + g*512 + p] = B[g,p,h]
// 1M elements, trivial cost.
// ---------------------------------------------------------------------------
__global__ void prep_weights_kernel(const float* __restrict__ A,
                                    const float* __restrict__ B) {
    int id = blockIdx.x * blockDim.x + threadIdx.x;   // over G*H*H = 1048576
    int g   = id >> 18;                 // / (512*512)
    int rem = id & ((H_DIM * H_DIM) - 1);
    int p   = rem >> 9;
    int h   = rem & (H_DIM - 1);
    float a = A[id];
    float b = B[id];
    int o = h * N_COLS + g * H_DIM + p;
    g_Wt[o] = a - b;
    g_Bt[o] = b;
}

// ---------------------------------------------------------------------------
// S[b,h] = sum_{k=0..7} x[b, k*512 + h].  Coalesced along h.
// ---------------------------------------------------------------------------
__global__ void compute_S_kernel(const float* __restrict__ x, int bsz) {
    int id = blockIdx.x * blockDim.x + threadIdx.x;   // bsz*512 threads
    if (id >= bsz * H_DIM) return;
    int b = id >> 9;
    int h = id & (H_DIM - 1);
    const float* xp = x + (size_t)b * (K_BLK * H_DIM) + h;
    float s = 0.f;
#pragma unroll
    for (int k = 0; k < K_BLK; ++k) s += xp[k * H_DIM];
    g_S[id] = s;
}

// ---------------------------------------------------------------------------
// Tiled SGEMM: C = A[MxK] * B[KxN], both row-major, K%16==0, tiles exact.
// BM=BN=128, BK=16, 256 threads, 8x8 per thread, float4 everywhere.
// MAIN epilogue: adds g_T[row>>3, col] and writes to the remapped output
//   out[(row>>3)*16384 + (col>>9)*4096 + (row&7)*512 + (col&511)]
// Non-MAIN epilogue: plain row-major store (used to produce g_T).
// ---------------------------------------------------------------------------
#define BM 128
#define BN 128
#define BK 16
#define TM 8
#define TN 8
#define PAD 4   // As row padding: kills 4-way store conflicts, keeps 16B align

template <bool MAIN>
__global__ __launch_bounds__(256, 2)
void sgemm_kernel(const float* __restrict__ Amat,
                  const float* __restrict__ Bmat,
                  float* __restrict__ C,
                  int M, int N, int K) {
    __shared__ __align__(16) float As[BK][BM + PAD];   // transposed A tile
    __shared__ __align__(16) float Bs[BK][BN];

    const int tid  = threadIdx.x;
    const int cRow = blockIdx.y;
    const int cCol = blockIdx.x;

    const int threadRow = tid / (BN / TN);   // 0..15
    const int threadCol = tid % (BN / TN);   // 0..15

    // A tile loads: BM x BK, float4 (BK/4 = 4 vec per row), 64 rows/pass, 2 passes
    const int innerRowA = tid / (BK / 4);    // 0..63
    const int innerColA = tid % (BK / 4);    // 0..3
    // B tile loads: BK x BN, float4 (BN/4 = 32 vec per row), 8 rows/pass, 2 passes
    const int innerRowB = tid / (BN / 4);    // 0..7
    const int innerColB = tid % (BN / 4);    // 0..31

    const float* Aptr = Amat + (size_t)cRow * BM * K;
    const float* Bptr = Bmat + (size_t)cCol * BN;

    float acc[TM][TN];
#pragma unroll
    for (int i = 0; i < TM; ++i)
#pragma unroll
        for (int j = 0; j < TN; ++j) acc[i][j] = 0.f;

    for (int kb = 0; kb < K; kb += BK) {
        // ---- stage A (transposed) ----
#pragma unroll
        for (int off = 0; off < BM; off += 64) {
            float4 t = *reinterpret_cast<const float4*>(
                Aptr + (size_t)(innerRowA + off) * K + kb + innerColA * 4);
            As[innerColA * 4 + 0][innerRowA + off] = t.x;
            As[innerColA * 4 + 1][innerRowA + off] = t.y;
            As[innerColA * 4 + 2][innerRowA + off] = t.z;
            As[innerColA * 4 + 3][innerRowA + off] = t.w;
        }
        // ---- stage B ----
#pragma unroll
        for (int off = 0; off < BK; off += 8) {
            *reinterpret_cast<float4*>(&Bs[innerRowB + off][innerColB * 4]) =
                *reinterpret_cast<const float4*>(
                    Bptr + (size_t)(kb + innerRowB + off) * N + innerColB * 4);
        }
        __syncthreads();

        // ---- compute ----
#pragma unroll
        for (int k = 0; k < BK; ++k) {
            float4 m0 = *reinterpret_cast<const float4*>(&As[k][threadRow * TM]);
            float4 m1 = *reinterpret_cast<const float4*>(&As[k][threadRow * TM + 4]);
            float4 n0 = *reinterpret_cast<const float4*>(&Bs[k][threadCol * TN]);
            float4 n1 = *reinterpret_cast<const float4*>(&Bs[k][threadCol * TN + 4]);
            float regM[TM] = {m0.x, m0.y, m0.z, m0.w, m1.x, m1.y, m1.z, m1.w};
            float regN[TN] = {n0.x, n0.y, n0.z, n0.w, n1.x, n1.y, n1.z, n1.w};
#pragma unroll
            for (int i = 0; i < TM; ++i)
#pragma unroll
                for (int j = 0; j < TN; ++j)
                    acc[i][j] += regM[i] * regN[j];
        }
        __syncthreads();
    }

    // ---- epilogue ----
#pragma unroll
    for (int i = 0; i < TM; ++i) {
        const int row = cRow * BM + threadRow * TM + i;
#pragma unroll
        for (int j = 0; j < TN; j += 4) {
            const int col = cCol * BN + threadCol * TN + j;
            float4 v = make_float4(acc[i][j], acc[i][j + 1], acc[i][j + 2], acc[i][j + 3]);
            if (MAIN) {
                const int b = row >> 3;                // batch
                const int k = row & 7;                 // block index
                const float4 t = *reinterpret_cast<const float4*>(
                    &g_T[(size_t)b * N_COLS + col]);
                v.x += t.x; v.y += t.y; v.z += t.z; v.w += t.w;
                // out[b, g*4096 + k*512 + p], col = g*512 + p (tile never straddles g)
                const size_t oidx = (size_t)b * (G_DIM * K_BLK * H_DIM)
                                  + (size_t)(col >> 9) * (K_BLK * H_DIM)
                                  + (size_t)k * H_DIM
                                  + (col & (H_DIM - 1));
                *reinterpret_cast<float4*>(C + oidx) = v;
            } else {
                *reinterpret_cast<float4*>(C + (size_t)row * N + col) = v;
            }
        }
    }
}

// ---------------------------------------------------------------------------
// Launch
// ---------------------------------------------------------------------------
extern "C" void kernel_launch(void* const* d_in, const int* in_sizes, int n_in,
                              void* d_out, int out_size) {
    const float* x = (const float*)d_in[0];   // [bsz, 4096]
    const float* A = (const float*)d_in[1];   // [4, 512, 512]
    const float* B = (const float*)d_in[2];   // [4, 512, 512]
    float* out = (float*)d_out;

    const int bsz = in_sizes[0] / (K_BLK * H_DIM);   // 4096
    const int M_main = bsz * K_BLK;                  // 32768

    // Resolve scratch addresses (no allocation; address-of __device__ symbols).
    float *Wt, *Bt, *S, *T;
    cudaGetSymbolAddress((void**)&Wt, g_Wt);
    cudaGetSymbolAddress((void**)&Bt, g_Bt);
    cudaGetSymbolAddress((void**)&S,  g_S);
    cudaGetSymbolAddress((void**)&T,  g_T);

    // 1) weight transpose + (A-B)
    {
        int total = G_DIM * H_DIM * H_DIM;           // 1048576
        prep_weights_kernel<<<total / 256, 256>>>(A, B);
    }
    // 2) S = sum_k x3
    {
        int total = bsz * H_DIM;
        compute_S_kernel<<<(total + 255) / 256, 256>>>(x, bsz);
    }
    // 3) T = S @ Bt   [bsz x 2048]
    {
        dim3 grid(N_COLS / BN, bsz / BM);
        sgemm_kernel<false><<<grid, 256>>>(S, Bt, T, bsz, N_COLS, H_DIM);
    }
    // 4) out = remap(X @ Wt + broadcast T)
    {
        dim3 grid(N_COLS / BN, M_main / BM);
        sgemm_kernel<true><<<grid, 256>>>(x, Wt, out, M_main, N_COLS, H_DIM);
    }
}

// round 10
// speedup vs baseline: 2.1224x; 2.1224x over previous
#include <cuda_runtime.h>
#include <cuda_bf16.h>
#include <cstdint>

// Problem: x [4096, 4096] fp32, A/B [4, 512, 512] fp32 -> out [4096, 16384] fp32
#define G_DIM 4
#define K_BLK 8
#define H_DIM 512
#define N_COLS 2048            // G*H: GEMM output columns (n = g*512 + p)
#define BSZ 4096
#define M_MAIN 32768           // BSZ * K_BLK
#define KDIM 512

// GEMM tiling (mma.sync path, base ISA only — no 'a' features)
#define BM 128
#define BN 128
#define BK 32                  // K elems per stage chunk (64 B bf16 rows)
#define KSTEPS (KDIM / BK)     // 16
#define NTHREADS 256
#define NSTAGES 4
#define TILE_B 8192            // 128 rows x 64 B
#define STAGE_B (4 * TILE_B)   // Ahi, Alo, Bhi, Blo = 32 KB
#define SMEM_REQ (NSTAGES * STAGE_B)   // 131072

// ---------------------------------------------------------------------------
// Static device scratch (no runtime allocation allowed)
// ---------------------------------------------------------------------------
__device__ __nv_bfloat16 g_Xhi[(size_t)M_MAIN * KDIM];
__device__ __nv_bfloat16 g_Xlo[(size_t)M_MAIN * KDIM];
__device__ __nv_bfloat16 g_Whi[(size_t)N_COLS * KDIM];   // (A-B)
__device__ __nv_bfloat16 g_Wlo[(size_t)N_COLS * KDIM];
__device__ __nv_bfloat16 g_Bhi[(size_t)N_COLS * KDIM];   // B
__device__ __nv_bfloat16 g_Blo[(size_t)N_COLS * KDIM];
__device__ __nv_bfloat16 g_Shi[(size_t)BSZ * KDIM];      // sum_k x3
__device__ __nv_bfloat16 g_Slo[(size_t)BSZ * KDIM];
__device__ float         g_T  [(size_t)BSZ * N_COLS];    // T = S @ B^T

// ---------------------------------------------------------------------------
// Base-ISA PTX helpers (sm_80-class: cp.async / ldmatrix / mma.sync)
// ---------------------------------------------------------------------------
__device__ __forceinline__ uint32_t smem_u32(const void* p) {
    return (uint32_t)__cvta_generic_to_shared(p);
}

__device__ __forceinline__ void cp16(uint32_t dst, const void* src) {
    asm volatile("cp.async.cg.shared.global [%0], [%1], 16;"
                 :: "r"(dst), "l"(src) : "memory");
}
__device__ __forceinline__ void cp_commit() {
    asm volatile("cp.async.commit_group;" ::: "memory");
}
template <int N>
__device__ __forceinline__ void cp_wait() {
    asm volatile("cp.async.wait_group %0;" :: "n"(N) : "memory");
}

__device__ __forceinline__ void ldsm4(uint32_t* r, uint32_t a) {
    asm volatile("ldmatrix.sync.aligned.m8n8.x4.shared.b16 {%0,%1,%2,%3}, [%4];"
                 : "=r"(r[0]), "=r"(r[1]), "=r"(r[2]), "=r"(r[3]) : "r"(a));
}

__device__ __forceinline__ void mma_bf16(float* c, const uint32_t* a,
                                         uint32_t b0, uint32_t b1) {
    asm volatile(
        "mma.sync.aligned.m16n8k16.row.col.f32.bf16.bf16.f32 "
        "{%0,%1,%2,%3}, {%4,%5,%6,%7}, {%8,%9}, {%0,%1,%2,%3};"
        : "+f"(c[0]), "+f"(c[1]), "+f"(c[2]), "+f"(c[3])
        : "r"(a[0]), "r"(a[1]), "r"(a[2]), "r"(a[3]), "r"(b0), "r"(b1));
}

// Swizzled smem offset for a 16B chunk: rows of 64 B, chunk c in 0..3.
// c' = c ^ ((row>>1)&3): conflict-free for both cp.async stores and ldmatrix.
__device__ __forceinline__ uint32_t sw_off(int row, int c) {
    return (uint32_t)(row * 64 + ((c ^ ((row >> 1) & 3)) << 4));
}

// ---------------------------------------------------------------------------
// Prep kernels
// ---------------------------------------------------------------------------
__global__ void prep_w_kernel(const float* __restrict__ A, const float* __restrict__ B) {
    int id = blockIdx.x * blockDim.x + threadIdx.x;   // 1048576
    float a = A[id], b = B[id];
    float w = a - b;
    __nv_bfloat16 wh = __float2bfloat16(w);
    g_Whi[id] = wh;
    g_Wlo[id] = __float2bfloat16(w - __bfloat162float(wh));
    __nv_bfloat16 bh = __float2bfloat16(b);
    g_Bhi[id] = bh;
    g_Blo[id] = __float2bfloat16(b - __bfloat162float(bh));
}

__global__ void prep_x_kernel(const float* __restrict__ x) {
    int id = blockIdx.x * blockDim.x + threadIdx.x;   // 4194304 (x4 vec)
    float4 v = reinterpret_cast<const float4*>(x)[id];
    __nv_bfloat16 h0 = __float2bfloat16(v.x), h1 = __float2bfloat16(v.y);
    __nv_bfloat16 h2 = __float2bfloat16(v.z), h3 = __float2bfloat16(v.w);
    __nv_bfloat16 l0 = __float2bfloat16(v.x - __bfloat162float(h0));
    __nv_bfloat16 l1 = __float2bfloat16(v.y - __bfloat162float(h1));
    __nv_bfloat16 l2 = __float2bfloat16(v.z - __bfloat162float(h2));
    __nv_bfloat16 l3 = __float2bfloat16(v.w - __bfloat162float(h3));
    __nv_bfloat162* Hi = reinterpret_cast<__nv_bfloat162*>(g_Xhi);
    __nv_bfloat162* Lo = reinterpret_cast<__nv_bfloat162*>(g_Xlo);
    Hi[2 * id]     = __halves2bfloat162(h0, h1);
    Hi[2 * id + 1] = __halves2bfloat162(h2, h3);
    Lo[2 * id]     = __halves2bfloat162(l0, l1);
    Lo[2 * id + 1] = __halves2bfloat162(l2, l3);
}

__global__ void compute_S_kernel(const float* __restrict__ x) {
    int id = blockIdx.x * blockDim.x + threadIdx.x;   // 2097152
    int b = id >> 9;
    int h = id & (H_DIM - 1);
    const float* xp = x + (size_t)b * (K_BLK * H_DIM) + h;
    float s = 0.f;
#pragma unroll
    for (int k = 0; k < K_BLK; ++k) s += xp[k * H_DIM];
    __nv_bfloat16 hi = __float2bfloat16(s);
    g_Shi[id] = hi;
    g_Slo[id] = __float2bfloat16(s - __bfloat162float(hi));
}

// ---------------------------------------------------------------------------
// mma.sync GEMM: D[BM,BN] = A[M,K] * B[N,K]^T, 3-pass bf16 hi/lo, f32 acc.
// 8 warps (2x4), warp tile 64x32, 4-stage cp.async pipeline.
// MAIN: out[b, g*4096 + kb*512 + p] = D + T[b, n];  else row-major D store.
// ---------------------------------------------------------------------------
template <bool MAIN>
__global__ void __launch_bounds__(NTHREADS, 1)
mma_gemm_kernel(const __nv_bfloat16* __restrict__ Ahi,
                const __nv_bfloat16* __restrict__ Alo,
                const __nv_bfloat16* __restrict__ Bhi,
                const __nv_bfloat16* __restrict__ Blo,
                const float* __restrict__ Tadd,
                float* __restrict__ outp)
{
    extern __shared__ __align__(128) char smem[];
    const uint32_t sbase = smem_u32(smem);

    const int tid  = threadIdx.x;
    const int lane = tid & 31;
    const int wid  = tid >> 5;
    const int wm   = wid >> 2;          // 0..1  -> 64-row slab
    const int wn   = wid & 3;           // 0..3  -> 32-col slab

    // ---- staging geometry: each thread copies 2 chunks (16 B) per tile ----
    const int r0 = tid >> 2;            // 0..63
    const int r1 = r0 + 64;
    const int c0 = tid & 3;
    const uint32_t d0 = sw_off(r0, c0);
    const uint32_t d1 = sw_off(r1, c0);
    const size_t oA0 = (size_t)(blockIdx.y * BM + r0) * KDIM + c0 * 8;
    const size_t oA1 = (size_t)(blockIdx.y * BM + r1) * KDIM + c0 * 8;
    const size_t oB0 = (size_t)(blockIdx.x * BN + r0) * KDIM + c0 * 8;
    const size_t oB1 = (size_t)(blockIdx.x * BN + r1) * KDIM + c0 * 8;

    // ---- ldmatrix geometry ----
    const int lr = lane & 15;           // row within 16-row fragment
    const int lc = lane >> 4;           // which 16B k-chunk (0/1) of the k16
    uint32_t aoff[4], asw[4];
#pragma unroll
    for (int mf = 0; mf < 4; ++mf) {
        const int row = wm * 64 + mf * 16 + lr;
        aoff[mf] = (uint32_t)(row * 64);
        asw[mf]  = (uint32_t)(((row >> 1) & 3) << 4);
    }
    uint32_t boff[2], bsw[2];
#pragma unroll
    for (int nb = 0; nb < 2; ++nb) {
        const int row = wn * 32 + nb * 16 + lr;
        boff[nb] = (uint32_t)(row * 64);
        bsw[nb]  = (uint32_t)(((row >> 1) & 3) << 4);
    }

    float acc[4][4][4];
#pragma unroll
    for (int i = 0; i < 4; ++i)
#pragma unroll
        for (int j = 0; j < 4; ++j)
#pragma unroll
            for (int e = 0; e < 4; ++e) acc[i][j][e] = 0.f;

    // ---- stage loader ----
    auto load_stage = [&](int s, int kc) {
        const uint32_t sb = sbase + (uint32_t)((s & 3) * STAGE_B);
        const size_t ke = (size_t)kc * BK;
        cp16(sb + d0,              Ahi + oA0 + ke);
        cp16(sb + d1,              Ahi + oA1 + ke);
        cp16(sb + TILE_B + d0,     Alo + oA0 + ke);
        cp16(sb + TILE_B + d1,     Alo + oA1 + ke);
        cp16(sb + 2 * TILE_B + d0, Bhi + oB0 + ke);
        cp16(sb + 2 * TILE_B + d1, Bhi + oB1 + ke);
        cp16(sb + 3 * TILE_B + d0, Blo + oB0 + ke);
        cp16(sb + 3 * TILE_B + d1, Blo + oB1 + ke);
    };

    // ---- prologue: fill stages 0..2 ----
#pragma unroll
    for (int s = 0; s < NSTAGES - 1; ++s) { load_stage(s, s); cp_commit(); }

    // ---- main loop ----
#pragma unroll 1
    for (int kc = 0; kc < KSTEPS; ++kc) {
        if (kc + NSTAGES - 1 < KSTEPS) load_stage(kc + NSTAGES - 1, kc + NSTAGES - 1);
        cp_commit();
        cp_wait<NSTAGES - 1>();        // stage kc resident
        __syncthreads();

        const uint32_t sb = sbase + (uint32_t)((kc & 3) * STAGE_B);
#pragma unroll
        for (int h = 0; h < 2; ++h) {  // two k16 steps per BK=32
            const uint32_t csel = (uint32_t)((2 * h + lc) << 4);
            uint32_t ah[4][4], al[4][4], bh[2][4], bl[2][4];
#pragma unroll
            for (int mf = 0; mf < 4; ++mf) {
                const uint32_t ad = sb + aoff[mf] + (csel ^ asw[mf]);
                ldsm4(ah[mf], ad);
                ldsm4(al[mf], ad + TILE_B);
            }
#pragma unroll
            for (int nb = 0; nb < 2; ++nb) {
                const uint32_t bd = sb + 2 * TILE_B + boff[nb] + (csel ^ bsw[nb]);
                ldsm4(bh[nb], bd);
                ldsm4(bl[nb], bd + TILE_B);
            }
#pragma unroll
            for (int mf = 0; mf < 4; ++mf) {
#pragma unroll
                for (int n8 = 0; n8 < 4; ++n8) {
                    const uint32_t bh0 = bh[n8 >> 1][n8 & 1];
                    const uint32_t bh1 = bh[n8 >> 1][(n8 & 1) + 2];
                    const uint32_t bl0 = bl[n8 >> 1][n8 & 1];
                    const uint32_t bl1 = bl[n8 >> 1][(n8 & 1) + 2];
                    mma_bf16(acc[mf][n8], ah[mf], bh0, bh1);   // hi*hi
                    mma_bf16(acc[mf][n8], ah[mf], bl0, bl1);   // hi*lo
                    mma_bf16(acc[mf][n8], al[mf], bh0, bh1);   // lo*hi
                }
            }
        }
        __syncthreads();               // reads done before buffer reuse
    }

    // ---- epilogue: direct sector-aligned float2 stores ----
    const int m0base = blockIdx.y * BM + wm * 64;
    const int n0base = blockIdx.x * BN + wn * 32;
#pragma unroll
    for (int mf = 0; mf < 4; ++mf) {
#pragma unroll
        for (int n8 = 0; n8 < 4; ++n8) {
            const int n = n0base + n8 * 8 + 2 * (lane & 3);
#pragma unroll
            for (int hf = 0; hf < 2; ++hf) {
                const int m = m0base + mf * 16 + (lane >> 2) + hf * 8;
                float2 v = make_float2(acc[mf][n8][2 * hf], acc[mf][n8][2 * hf + 1]);
                if (MAIN) {
                    const int b  = m >> 3;
                    const int kb = m & 7;
                    const float2 t = *reinterpret_cast<const float2*>(
                        Tadd + (size_t)b * N_COLS + n);
                    v.x += t.x; v.y += t.y;
                    const size_t o = (size_t)b * (G_DIM * K_BLK * H_DIM)
                                   + (size_t)(n >> 9) * (K_BLK * H_DIM)
                                   + (size_t)kb * H_DIM + (n & (H_DIM - 1));
                    *reinterpret_cast<float2*>(outp + o) = v;
                } else {
                    *reinterpret_cast<float2*>(outp + (size_t)m * N_COLS + n) = v;
                }
            }
        }
    }
}

// ---------------------------------------------------------------------------
// Launch
// ---------------------------------------------------------------------------
extern "C" void kernel_launch(void* const* d_in, const int* in_sizes, int n_in,
                              void* d_out, int out_size) {
    const float* x = (const float*)d_in[0];
    const float* A = (const float*)d_in[1];
    const float* B = (const float*)d_in[2];
    float* out = (float*)d_out;

    __nv_bfloat16 *Xhi, *Xlo, *Whi, *Wlo, *Bhi, *Blo, *Shi, *Slo;
    float* T;
    cudaGetSymbolAddress((void**)&Xhi, g_Xhi);
    cudaGetSymbolAddress((void**)&Xlo, g_Xlo);
    cudaGetSymbolAddress((void**)&Whi, g_Whi);
    cudaGetSymbolAddress((void**)&Wlo, g_Wlo);
    cudaGetSymbolAddress((void**)&Bhi, g_Bhi);
    cudaGetSymbolAddress((void**)&Blo, g_Blo);
    cudaGetSymbolAddress((void**)&Shi, g_Shi);
    cudaGetSymbolAddress((void**)&Slo, g_Slo);
    cudaGetSymbolAddress((void**)&T,   g_T);

    cudaFuncSetAttribute(mma_gemm_kernel<true>,
                         cudaFuncAttributeMaxDynamicSharedMemorySize, SMEM_REQ);
    cudaFuncSetAttribute(mma_gemm_kernel<false>,
                         cudaFuncAttributeMaxDynamicSharedMemorySize, SMEM_REQ);

    // 1) weight split (A-B, B) -> bf16 hi/lo
    prep_w_kernel<<<(G_DIM * H_DIM * H_DIM) / 256, 256>>>(A, B);
    // 2) x split -> bf16 hi/lo
    prep_x_kernel<<<(M_MAIN * KDIM / 4) / 256, 256>>>(x);
    // 3) S = sum_k x3, split
    compute_S_kernel<<<(BSZ * H_DIM) / 256, 256>>>(x);
    // 4) T = S @ B^T                      [4096 x 2048]
    mma_gemm_kernel<false><<<dim3(N_COLS / BN, BSZ / BM), NTHREADS, SMEM_REQ>>>(
        Shi, Slo, Bhi, Blo, nullptr, T);
    // 5) out = remap(X @ (A-B)^T + T)     [32768 x 2048]
    mma_gemm_kernel<true><<<dim3(N_COLS / BN, M_MAIN / BM), NTHREADS, SMEM_REQ>>>(
        Xhi, Xlo, Whi, Wlo, T, out);
}